// round 2
// baseline (speedup 1.0000x reference)
#include <cuda_runtime.h>
#include <math.h>

// Problem dims (fixed by setup_inputs)
#define BATCH 256
#define DM    512
#define NN    1024
#define KTOT  (2*NN)        // concat [cos_sum | sin_sum] along K

// Phase-1 tiling: 32x32 (batch x neuron) tile, 256 threads, 2x2 per thread
#define BT 32
#define NT 32
#define DC 64
#define P1_THREADS 256

// Phase-2 tiling (split-K SGEMM)
#define BM 64               // batch rows per block
#define BN 64               // out features per block
#define BK 16
#define SPLITK 8
#define KCHUNK (KTOT / SPLITK)   // 256

// Scratch (static device globals — no allocation allowed)
__device__ float g_sums[BATCH * KTOT];            // [b][k]: k<NN cos_sum, k>=NN sin_sum
__device__ float g_part[SPLITK * BATCH * DM];     // split-K partials

// ---------------------------------------------------------------------------
// Packed f32x2 helpers (Blackwell)
// ---------------------------------------------------------------------------
__device__ __forceinline__ unsigned long long pack2(float lo, float hi) {
    unsigned long long r;
    asm("mov.b64 %0, {%1, %2};" : "=l"(r) : "f"(lo), "f"(hi));
    return r;
}
__device__ __forceinline__ void unpack2(unsigned long long v, float& lo, float& hi) {
    asm("mov.b64 {%0, %1}, %2;" : "=f"(lo), "=f"(hi) : "l"(v));
}
__device__ __forceinline__ void fma2(unsigned long long& d, unsigned long long a,
                                     unsigned long long b) {
    asm("fma.rn.f32x2 %0, %1, %2, %3;" : "=l"(d) : "l"(a), "l"(b), "l"(d));
}

// ---------------------------------------------------------------------------
// Phase 1: resonance sums.  theta = x/(1+|W|) + B; accumulate sin/cos.
// Block: 256 threads over a 32(batch) x 32(neuron) tile, 2x2 per thread.
// d staged in chunks of 64 through shared memory.
// Grid: (NN/32=32, BATCH/32=8) = 256 blocks.
// ---------------------------------------------------------------------------
__global__ void __launch_bounds__(P1_THREADS) phase1_kernel(
    const float* __restrict__ xr, const float* __restrict__ xi,
    const float* __restrict__ W,  const float* __restrict__ Bm)
{
    __shared__ float xs[BT][DC + 1];   // stride 65: rows 2 apart -> banks 2i mod 32
    __shared__ float ws[NT][DC + 1];
    __shared__ float bs[NT][DC + 1];

    const int t  = threadIdx.x;
    const int tn = t & 15;             // neuron pair index (2 neurons)
    const int tb = t >> 4;             // batch pair index  (2 batches)
    const int b0 = blockIdx.y * BT;
    const int n0 = blockIdx.x * NT;

    float aS00 = 0.f, aS01 = 0.f, aS10 = 0.f, aS11 = 0.f;
    float aC00 = 0.f, aC01 = 0.f, aC10 = 0.f, aC11 = 0.f;

    for (int d0 = 0; d0 < DM; d0 += DC) {
        // Stage 32x64 of each array; 8 scalar iters per thread per array.
        #pragma unroll
        for (int i = t; i < BT * DC; i += P1_THREADS) {
            const int r = i >> 6;        // row within tile
            const int c = i & (DC - 1);  // col within chunk
            const int gx = (b0 + r) * DM + d0 + c;
            xs[r][c] = xr[gx] + xi[gx];
            const int gw = (n0 + r) * DM + d0 + c;
            ws[r][c] = __fdividef(1.0f, 1.0f + fabsf(W[gw]));
            bs[r][c] = Bm[gw];
        }
        __syncthreads();

        #pragma unroll 8
        for (int d = 0; d < DC; d++) {
            const float x0  = xs[2 * tb][d];
            const float x1  = xs[2 * tb + 1][d];
            const float w0  = ws[2 * tn][d];
            const float w1  = ws[2 * tn + 1][d];
            const float bb0 = bs[2 * tn][d];
            const float bb1 = bs[2 * tn + 1][d];
            float s, c;
            __sincosf(fmaf(x0, w0, bb0), &s, &c); aS00 += s; aC00 += c;
            __sincosf(fmaf(x0, w1, bb1), &s, &c); aS01 += s; aC01 += c;
            __sincosf(fmaf(x1, w0, bb0), &s, &c); aS10 += s; aC10 += c;
            __sincosf(fmaf(x1, w1, bb1), &s, &c); aS11 += s; aC11 += c;
        }
        __syncthreads();
    }

    const int br0 = b0 + 2 * tb, br1 = br0 + 1;
    const int nc0 = n0 + 2 * tn, nc1 = nc0 + 1;
    g_sums[br0 * KTOT + nc0]      = aC00;
    g_sums[br0 * KTOT + nc1]      = aC01;
    g_sums[br1 * KTOT + nc0]      = aC10;
    g_sums[br1 * KTOT + nc1]      = aC11;
    g_sums[br0 * KTOT + NN + nc0] = aS00;
    g_sums[br0 * KTOT + NN + nc1] = aS01;
    g_sums[br1 * KTOT + NN + nc0] = aS10;
    g_sums[br1 * KTOT + NN + nc1] = aS11;
}

// ---------------------------------------------------------------------------
// Phase 2: split-K SGEMM with packed f32x2 FMA.
//   out[b][m] = sum_k A[b][k] * Wsel[m][k'];  A = g_sums (256 x 2048)
// Each block: 64x64 tile over a 256-wide K slab; 4x4 per thread (as 4x2 pairs).
// Grid: (DM/64=8, BATCH/64=4, SPLITK=8) = 256 blocks x 256 threads.
// ---------------------------------------------------------------------------
__global__ void __launch_bounds__(256) phase2_kernel(
    const float* __restrict__ PC, const float* __restrict__ PS)
{
    __shared__ float As[BK][BM + 4];   // [k][b], 16B-aligned rows
    __shared__ float Bs[BK][BN + 4];   // [k][m]

    const int t  = threadIdx.x;
    const int tx = t & 15;             // -> 4 output columns (m)
    const int ty = t >> 4;             // -> 4 output rows (b)
    const int m0 = blockIdx.x * BN;
    const int b0 = blockIdx.y * BM;
    const int z  = blockIdx.z;
    const int kbase = z * KCHUNK;

    const float* __restrict__ Wsel = (kbase < NN) ? PC : PS;
    const int koff = (kbase < NN) ? 0 : NN;

    unsigned long long acc2[4][2];
    #pragma unroll
    for (int i = 0; i < 4; i++) { acc2[i][0] = 0ull; acc2[i][1] = 0ull; }

    for (int k0 = kbase; k0 < kbase + KCHUNK; k0 += BK) {
        #pragma unroll
        for (int i = t; i < BM * BK; i += 256) {
            const int r  = i >> 4;
            const int kk = i & 15;
            As[kk][r] = g_sums[(b0 + r) * KTOT + k0 + kk];
        }
        #pragma unroll
        for (int i = t; i < BN * BK; i += 256) {
            const int r  = i >> 4;
            const int kk = i & 15;
            Bs[kk][r] = Wsel[(m0 + r) * NN + (k0 + kk - koff)];
        }
        __syncthreads();

        #pragma unroll
        for (int kk = 0; kk < BK; kk++) {
            const float4 av = *(const float4*)&As[kk][ty * 4];
            const float4 bv = *(const float4*)&Bs[kk][tx * 4];
            const unsigned long long b01 = pack2(bv.x, bv.y);
            const unsigned long long b23 = pack2(bv.z, bv.w);
            const float a[4] = {av.x, av.y, av.z, av.w};
            #pragma unroll
            for (int i = 0; i < 4; i++) {
                const unsigned long long ai = pack2(a[i], a[i]);
                fma2(acc2[i][0], ai, b01);
                fma2(acc2[i][1], ai, b23);
            }
        }
        __syncthreads();
    }

    float* outp = &g_part[z * BATCH * DM];
    #pragma unroll
    for (int i = 0; i < 4; i++) {
        float v0, v1, v2, v3;
        unpack2(acc2[i][0], v0, v1);
        unpack2(acc2[i][1], v2, v3);
        float4* dst = (float4*)&outp[(b0 + ty * 4 + i) * DM + m0 + tx * 4];
        *dst = make_float4(v0, v1, v2, v3);
    }
}

// ---------------------------------------------------------------------------
// Phase 3: reduce split-K partials + SiLU (float4 vectorized).
// ---------------------------------------------------------------------------
__global__ void __launch_bounds__(256) phase3_kernel(float* __restrict__ out)
{
    const int i = (blockIdx.x * 256 + threadIdx.x) * 4;
    if (i >= BATCH * DM) return;
    float4 v = make_float4(0.f, 0.f, 0.f, 0.f);
    #pragma unroll
    for (int zz = 0; zz < SPLITK; zz++) {
        const float4 p = *(const float4*)&g_part[zz * BATCH * DM + i];
        v.x += p.x; v.y += p.y; v.z += p.z; v.w += p.w;
    }
    float4 o;
    o.x = v.x / (1.0f + __expf(-v.x));
    o.y = v.y / (1.0f + __expf(-v.y));
    o.z = v.z / (1.0f + __expf(-v.z));
    o.w = v.w / (1.0f + __expf(-v.w));
    *(float4*)&out[i] = o;
}

extern "C" void kernel_launch(void* const* d_in, const int* in_sizes, int n_in,
                              void* d_out, int out_size)
{
    (void)in_sizes; (void)n_in; (void)out_size;
    const float* xr = (const float*)d_in[0];
    const float* xi = (const float*)d_in[1];
    const float* W  = (const float*)d_in[2];
    const float* Bm = (const float*)d_in[3];
    const float* PC = (const float*)d_in[4];
    const float* PS = (const float*)d_in[5];
    float* out = (float*)d_out;

    dim3 g1(NN / NT, BATCH / BT);              // 32 x 8 = 256 blocks
    phase1_kernel<<<g1, P1_THREADS>>>(xr, xi, W, Bm);

    dim3 g2(DM / BN, BATCH / BM, SPLITK);      // 8 x 4 x 8 = 256 blocks
    phase2_kernel<<<g2, 256>>>(PC, PS);

    phase3_kernel<<<(BATCH * DM / 4 + 255) / 256, 256>>>(out);
}

// round 3
// speedup vs baseline: 1.1719x; 1.1719x over previous
#include <cuda_runtime.h>
#include <math.h>

// Problem dims (fixed by setup_inputs)
#define BATCH 256
#define DM    512
#define NN    1024
#define KTOT  (2*NN)

// Phase-1 tiling: 32x32 (batch x neuron) tile, 256 threads, 2x2 per thread,
// d split across blockIdx.z into 4 slabs of 128 (2 chunks of DC=64 each).
#define BT 32
#define NT 32
#define DC 64
#define ZSPLIT 4
#define DPER (DM / ZSPLIT)       // 128
#define P1_THREADS 256

// Phase-2 tiling (split-K SGEMM)
#define BM 64
#define BN 64
#define BK 16
#define SPLITK 16
#define KCHUNK (KTOT / SPLITK)   // 128 (divides NN -> chunk never crosses cos/sin boundary)

// Scratch (static device globals — no allocation allowed)
__device__ float g_sumsP[ZSPLIT][BATCH * KTOT];   // phase-1 partials per d-slab (8 MB)
__device__ float g_sums[BATCH * KTOT];            // combined sums (2 MB)
__device__ float g_part[SPLITK * BATCH * DM];     // split-K GEMM partials (8 MB)

// ---------------------------------------------------------------------------
// Packed f32x2 helpers (Blackwell)
// ---------------------------------------------------------------------------
__device__ __forceinline__ unsigned long long pack2(float lo, float hi) {
    unsigned long long r;
    asm("mov.b64 %0, {%1, %2};" : "=l"(r) : "f"(lo), "f"(hi));
    return r;
}
__device__ __forceinline__ void unpack2(unsigned long long v, float& lo, float& hi) {
    asm("mov.b64 {%0, %1}, %2;" : "=f"(lo), "=f"(hi) : "l"(v));
}
__device__ __forceinline__ void fma2(unsigned long long& d, unsigned long long a,
                                     unsigned long long b) {
    asm("fma.rn.f32x2 %0, %1, %2, %3;" : "=l"(d) : "l"(a), "l"(b), "l"(d));
}

// ---------------------------------------------------------------------------
// Phase 1: resonance partial sums over one d-slab.
// Grid: (NN/32=32, BATCH/32=8, ZSPLIT=4) = 1024 blocks x 256 threads.
// smem transposed: per d, x-pair via one LDS.64, (w,b)x2 via one LDS.128.
// ---------------------------------------------------------------------------
__global__ void __launch_bounds__(P1_THREADS, 4) phase1_kernel(
    const float* __restrict__ xr, const float* __restrict__ xi,
    const float* __restrict__ W,  const float* __restrict__ Bm)
{
    __shared__ float xsT[DC][BT + 2];        // [d][b], stride 34 (even -> 8B-aligned pairs)
    __shared__ float wbT[DC][2 * NT + 4];    // [d][(w,b) interleaved], stride 132 (16B-aligned quads)

    const int t  = threadIdx.x;
    const int tn = t & 15;                   // neuron-pair index
    const int tb = t >> 4;                   // batch-pair index
    const int b0 = blockIdx.y * BT;
    const int n0 = blockIdx.x * NT;
    const int z  = blockIdx.z;
    const int zb = z * DPER;

    float aS00 = 0.f, aS01 = 0.f, aS10 = 0.f, aS11 = 0.f;
    float aC00 = 0.f, aC01 = 0.f, aC10 = 0.f, aC11 = 0.f;

    for (int d0 = zb; d0 < zb + DPER; d0 += DC) {
        // Stage 32 rows x 64 d into transposed smem (8 iters/thread).
        #pragma unroll
        for (int i = t; i < BT * DC; i += P1_THREADS) {
            const int r = i >> 6;            // row within tile
            const int c = i & (DC - 1);      // d within chunk
            const int gx = (b0 + r) * DM + d0 + c;
            xsT[c][r] = xr[gx] + xi[gx];
            const int gw = (n0 + r) * DM + d0 + c;
            const float winv = __fdividef(1.0f, 1.0f + fabsf(W[gw]));
            *(float2*)&wbT[c][2 * r] = make_float2(winv, Bm[gw]);
        }
        __syncthreads();

        #pragma unroll 8
        for (int d = 0; d < DC; d++) {
            const float2 xv = *(const float2*)&xsT[d][2 * tb];
            const float4 wb = *(const float4*)&wbT[d][4 * tn];
            // wb = (w_n0, b_n0, w_n1, b_n1)
            float s, c;
            __sincosf(fmaf(xv.x, wb.x, wb.y), &s, &c); aS00 += s; aC00 += c;
            __sincosf(fmaf(xv.x, wb.z, wb.w), &s, &c); aS01 += s; aC01 += c;
            __sincosf(fmaf(xv.y, wb.x, wb.y), &s, &c); aS10 += s; aC10 += c;
            __sincosf(fmaf(xv.y, wb.z, wb.w), &s, &c); aS11 += s; aC11 += c;
        }
        __syncthreads();
    }

    float* outp = g_sumsP[z];
    const int br0 = b0 + 2 * tb, br1 = br0 + 1;
    const int nc0 = n0 + 2 * tn, nc1 = nc0 + 1;
    outp[br0 * KTOT + nc0]      = aC00;
    outp[br0 * KTOT + nc1]      = aC01;
    outp[br1 * KTOT + nc0]      = aC10;
    outp[br1 * KTOT + nc1]      = aC11;
    outp[br0 * KTOT + NN + nc0] = aS00;
    outp[br0 * KTOT + NN + nc1] = aS01;
    outp[br1 * KTOT + NN + nc0] = aS10;
    outp[br1 * KTOT + NN + nc1] = aS11;
}

// ---------------------------------------------------------------------------
// Combine the 4 d-slab partials (float4 vectorized).
// ---------------------------------------------------------------------------
__global__ void __launch_bounds__(256) combine_kernel()
{
    const int i = (blockIdx.x * 256 + threadIdx.x) * 4;
    if (i >= BATCH * KTOT) return;
    float4 v = *(const float4*)&g_sumsP[0][i];
    #pragma unroll
    for (int zz = 1; zz < ZSPLIT; zz++) {
        const float4 p = *(const float4*)&g_sumsP[zz][i];
        v.x += p.x; v.y += p.y; v.z += p.z; v.w += p.w;
    }
    *(float4*)&g_sums[i] = v;
}

// ---------------------------------------------------------------------------
// Phase 2: split-K SGEMM with packed f32x2 FMA.
// Grid: (DM/64=8, BATCH/64=4, SPLITK=16) = 512 blocks x 256 threads.
// ---------------------------------------------------------------------------
__global__ void __launch_bounds__(256) phase2_kernel(
    const float* __restrict__ PC, const float* __restrict__ PS)
{
    __shared__ float As[BK][BM + 4];
    __shared__ float Bs[BK][BN + 4];

    const int t  = threadIdx.x;
    const int tx = t & 15;
    const int ty = t >> 4;
    const int m0 = blockIdx.x * BN;
    const int b0 = blockIdx.y * BM;
    const int z  = blockIdx.z;
    const int kbase = z * KCHUNK;

    const float* __restrict__ Wsel = (kbase < NN) ? PC : PS;
    const int koff = (kbase < NN) ? 0 : NN;

    unsigned long long acc2[4][2];
    #pragma unroll
    for (int i = 0; i < 4; i++) { acc2[i][0] = 0ull; acc2[i][1] = 0ull; }

    for (int k0 = kbase; k0 < kbase + KCHUNK; k0 += BK) {
        #pragma unroll
        for (int i = t; i < BM * BK; i += 256) {
            const int r  = i >> 4;
            const int kk = i & 15;
            As[kk][r] = g_sums[(b0 + r) * KTOT + k0 + kk];
        }
        #pragma unroll
        for (int i = t; i < BN * BK; i += 256) {
            const int r  = i >> 4;
            const int kk = i & 15;
            Bs[kk][r] = Wsel[(m0 + r) * NN + (k0 + kk - koff)];
        }
        __syncthreads();

        #pragma unroll
        for (int kk = 0; kk < BK; kk++) {
            const float4 av = *(const float4*)&As[kk][ty * 4];
            const float4 bv = *(const float4*)&Bs[kk][tx * 4];
            const unsigned long long b01 = pack2(bv.x, bv.y);
            const unsigned long long b23 = pack2(bv.z, bv.w);
            const float a[4] = {av.x, av.y, av.z, av.w};
            #pragma unroll
            for (int i = 0; i < 4; i++) {
                const unsigned long long ai = pack2(a[i], a[i]);
                fma2(acc2[i][0], ai, b01);
                fma2(acc2[i][1], ai, b23);
            }
        }
        __syncthreads();
    }

    float* outp = &g_part[z * BATCH * DM];
    #pragma unroll
    for (int i = 0; i < 4; i++) {
        float v0, v1, v2, v3;
        unpack2(acc2[i][0], v0, v1);
        unpack2(acc2[i][1], v2, v3);
        *(float4*)&outp[(b0 + ty * 4 + i) * DM + m0 + tx * 4] =
            make_float4(v0, v1, v2, v3);
    }
}

// ---------------------------------------------------------------------------
// Phase 3: reduce split-K partials + SiLU (float4 vectorized).
// ---------------------------------------------------------------------------
__global__ void __launch_bounds__(256) phase3_kernel(float* __restrict__ out)
{
    const int i = (blockIdx.x * 256 + threadIdx.x) * 4;
    if (i >= BATCH * DM) return;
    float4 v = make_float4(0.f, 0.f, 0.f, 0.f);
    #pragma unroll
    for (int zz = 0; zz < SPLITK; zz++) {
        const float4 p = *(const float4*)&g_part[zz * BATCH * DM + i];
        v.x += p.x; v.y += p.y; v.z += p.z; v.w += p.w;
    }
    float4 o;
    o.x = v.x / (1.0f + __expf(-v.x));
    o.y = v.y / (1.0f + __expf(-v.y));
    o.z = v.z / (1.0f + __expf(-v.z));
    o.w = v.w / (1.0f + __expf(-v.w));
    *(float4*)&out[i] = o;
}

extern "C" void kernel_launch(void* const* d_in, const int* in_sizes, int n_in,
                              void* d_out, int out_size)
{
    (void)in_sizes; (void)n_in; (void)out_size;
    const float* xr = (const float*)d_in[0];
    const float* xi = (const float*)d_in[1];
    const float* W  = (const float*)d_in[2];
    const float* Bm = (const float*)d_in[3];
    const float* PC = (const float*)d_in[4];
    const float* PS = (const float*)d_in[5];
    float* out = (float*)d_out;

    dim3 g1(NN / NT, BATCH / BT, ZSPLIT);      // 32 x 8 x 4 = 1024 blocks
    phase1_kernel<<<g1, P1_THREADS>>>(xr, xi, W, Bm);

    combine_kernel<<<(BATCH * KTOT / 4 + 255) / 256, 256>>>();

    dim3 g2(DM / BN, BATCH / BM, SPLITK);      // 8 x 4 x 16 = 512 blocks
    phase2_kernel<<<g2, 256>>>(PC, PS);

    phase3_kernel<<<(BATCH * DM / 4 + 255) / 256, 256>>>(out);
}

// round 4
// speedup vs baseline: 1.1765x; 1.0040x over previous
#include <cuda_runtime.h>
#include <math.h>

// Problem dims (fixed by setup_inputs)
#define BATCH 256
#define DM    512
#define NN    1024
#define KTOT  (2*NN)

// Phase-1 tiling: 32x32 (batch x neuron) tile, 256 threads, 2x2 per thread,
// d split across blockIdx.z into 8 slabs of 64 (exactly one staged chunk).
#define BT 32
#define NT 32
#define DC 64
#define ZSPLIT 8
#define DPER (DM / ZSPLIT)       // 64 == DC
#define P1_THREADS 256

// Phase-2 tiling (split-K SGEMM)
#define BM 64
#define BN 64
#define BK 16
#define SPLITK 16
#define KCHUNK (KTOT / SPLITK)   // 128

// Scratch (static device globals — no allocation allowed)
__device__ float g_sumsP[ZSPLIT][BATCH * KTOT];   // phase-1 partials per d-slab (16 MB)
__device__ float g_sums[BATCH * KTOT];            // combined sums (2 MB)
__device__ float g_part[SPLITK * BATCH * DM];     // split-K GEMM partials (8 MB)

// ---------------------------------------------------------------------------
// Packed f32x2 helpers (Blackwell)
// ---------------------------------------------------------------------------
__device__ __forceinline__ unsigned long long pack2(float lo, float hi) {
    unsigned long long r;
    asm("mov.b64 %0, {%1, %2};" : "=l"(r) : "f"(lo), "f"(hi));
    return r;
}
__device__ __forceinline__ void unpack2(unsigned long long v, float& lo, float& hi) {
    asm("mov.b64 {%0, %1}, %2;" : "=f"(lo), "=f"(hi) : "l"(v));
}
__device__ __forceinline__ void fma2(unsigned long long& d, unsigned long long a,
                                     unsigned long long b) {
    asm("fma.rn.f32x2 %0, %1, %2, %3;" : "=l"(d) : "l"(a), "l"(b), "l"(d));
}

// ---------------------------------------------------------------------------
// Phase 1: resonance partial sums over one 64-wide d-slab.
// Grid: (NN/32=32, BATCH/32=8, ZSPLIT=8) = 2048 blocks x 256 threads.
// Single staged chunk; per d: 1 LDS.64 (x pair) + 1 LDS.128 (w,b for 2 neurons),
// then 4 sincos pairs via MUFU.
// ---------------------------------------------------------------------------
__global__ void __launch_bounds__(P1_THREADS, 4) phase1_kernel(
    const float* __restrict__ xr, const float* __restrict__ xi,
    const float* __restrict__ W,  const float* __restrict__ Bm)
{
    __shared__ float xsT[DC][BT + 2];        // [d][b], stride 34
    __shared__ float wbT[DC][2 * NT + 4];    // [d][(w,b) interleaved], stride 132

    const int t  = threadIdx.x;
    const int tn = t & 15;                   // neuron-pair index
    const int tb = t >> 4;                   // batch-pair index
    const int b0 = blockIdx.y * BT;
    const int n0 = blockIdx.x * NT;
    const int z  = blockIdx.z;
    const int d0 = z * DPER;

    // Stage 32 rows x 64 d into transposed smem (8 iters/thread).
    #pragma unroll
    for (int i = t; i < BT * DC; i += P1_THREADS) {
        const int r = i >> 6;                // row within tile
        const int c = i & (DC - 1);          // d within chunk
        const int gx = (b0 + r) * DM + d0 + c;
        xsT[c][r] = xr[gx] + xi[gx];
        const int gw = (n0 + r) * DM + d0 + c;
        const float winv = __fdividef(1.0f, 1.0f + fabsf(W[gw]));
        *(float2*)&wbT[c][2 * r] = make_float2(winv, Bm[gw]);
    }
    __syncthreads();

    float aS00 = 0.f, aS01 = 0.f, aS10 = 0.f, aS11 = 0.f;
    float aC00 = 0.f, aC01 = 0.f, aC10 = 0.f, aC11 = 0.f;

    #pragma unroll 8
    for (int d = 0; d < DC; d++) {
        const float2 xv = *(const float2*)&xsT[d][2 * tb];
        const float4 wb = *(const float4*)&wbT[d][4 * tn];
        // wb = (w_n0, b_n0, w_n1, b_n1)
        float s, c;
        __sincosf(fmaf(xv.x, wb.x, wb.y), &s, &c); aS00 += s; aC00 += c;
        __sincosf(fmaf(xv.x, wb.z, wb.w), &s, &c); aS01 += s; aC01 += c;
        __sincosf(fmaf(xv.y, wb.x, wb.y), &s, &c); aS10 += s; aC10 += c;
        __sincosf(fmaf(xv.y, wb.z, wb.w), &s, &c); aS11 += s; aC11 += c;
    }

    float* outp = g_sumsP[z];
    const int br0 = b0 + 2 * tb, br1 = br0 + 1;
    const int nc0 = n0 + 2 * tn;             // even -> 8B aligned
    *(float2*)&outp[br0 * KTOT + nc0]      = make_float2(aC00, aC01);
    *(float2*)&outp[br1 * KTOT + nc0]      = make_float2(aC10, aC11);
    *(float2*)&outp[br0 * KTOT + NN + nc0] = make_float2(aS00, aS01);
    *(float2*)&outp[br1 * KTOT + NN + nc0] = make_float2(aS10, aS11);
}

// ---------------------------------------------------------------------------
// Combine the 8 d-slab partials. z-parallel: 2 threads per float4 output,
// each sums 4 slabs, shfl_xor(1) merge. Grid: 1024 blocks x 256.
// ---------------------------------------------------------------------------
__global__ void __launch_bounds__(256) combine_kernel()
{
    const int t = threadIdx.x;
    const int zg = t & 1;                        // 0 -> slabs 0..3, 1 -> 4..7
    const int o4 = blockIdx.x * 128 + (t >> 1);  // float4 index
    const int i  = o4 * 4;

    float4 v = make_float4(0.f, 0.f, 0.f, 0.f);
    #pragma unroll
    for (int j = 0; j < 4; j++) {
        const float4 p = *(const float4*)&g_sumsP[zg * 4 + j][i];
        v.x += p.x; v.y += p.y; v.z += p.z; v.w += p.w;
    }
    v.x += __shfl_xor_sync(0xFFFFFFFFu, v.x, 1);
    v.y += __shfl_xor_sync(0xFFFFFFFFu, v.y, 1);
    v.z += __shfl_xor_sync(0xFFFFFFFFu, v.z, 1);
    v.w += __shfl_xor_sync(0xFFFFFFFFu, v.w, 1);
    if (zg == 0) *(float4*)&g_sums[i] = v;
}

// ---------------------------------------------------------------------------
// Phase 2: split-K SGEMM with packed f32x2 FMA.
// Grid: (DM/64=8, BATCH/64=4, SPLITK=16) = 512 blocks x 256 threads.
// ---------------------------------------------------------------------------
__global__ void __launch_bounds__(256) phase2_kernel(
    const float* __restrict__ PC, const float* __restrict__ PS)
{
    __shared__ float As[BK][BM + 4];
    __shared__ float Bs[BK][BN + 4];

    const int t  = threadIdx.x;
    const int tx = t & 15;
    const int ty = t >> 4;
    const int m0 = blockIdx.x * BN;
    const int b0 = blockIdx.y * BM;
    const int z  = blockIdx.z;
    const int kbase = z * KCHUNK;

    const float* __restrict__ Wsel = (kbase < NN) ? PC : PS;
    const int koff = (kbase < NN) ? 0 : NN;

    unsigned long long acc2[4][2];
    #pragma unroll
    for (int i = 0; i < 4; i++) { acc2[i][0] = 0ull; acc2[i][1] = 0ull; }

    for (int k0 = kbase; k0 < kbase + KCHUNK; k0 += BK) {
        #pragma unroll
        for (int i = t; i < BM * BK; i += 256) {
            const int r  = i >> 4;
            const int kk = i & 15;
            As[kk][r] = g_sums[(b0 + r) * KTOT + k0 + kk];
        }
        #pragma unroll
        for (int i = t; i < BN * BK; i += 256) {
            const int r  = i >> 4;
            const int kk = i & 15;
            Bs[kk][r] = Wsel[(m0 + r) * NN + (k0 + kk - koff)];
        }
        __syncthreads();

        #pragma unroll
        for (int kk = 0; kk < BK; kk++) {
            const float4 av = *(const float4*)&As[kk][ty * 4];
            const float4 bv = *(const float4*)&Bs[kk][tx * 4];
            const unsigned long long b01 = pack2(bv.x, bv.y);
            const unsigned long long b23 = pack2(bv.z, bv.w);
            const float a[4] = {av.x, av.y, av.z, av.w};
            #pragma unroll
            for (int i = 0; i < 4; i++) {
                const unsigned long long ai = pack2(a[i], a[i]);
                fma2(acc2[i][0], ai, b01);
                fma2(acc2[i][1], ai, b23);
            }
        }
        __syncthreads();
    }

    float* outp = &g_part[z * BATCH * DM];
    #pragma unroll
    for (int i = 0; i < 4; i++) {
        float v0, v1, v2, v3;
        unpack2(acc2[i][0], v0, v1);
        unpack2(acc2[i][1], v2, v3);
        *(float4*)&outp[(b0 + ty * 4 + i) * DM + m0 + tx * 4] =
            make_float4(v0, v1, v2, v3);
    }
}

// ---------------------------------------------------------------------------
// Phase 3: reduce split-K partials + SiLU. z-parallel: 4 threads per float4
// output, each sums 4 of 16 slabs, shfl_xor(1)+(2) merge. Grid: 512 x 256.
// ---------------------------------------------------------------------------
__global__ void __launch_bounds__(256) phase3_kernel(float* __restrict__ out)
{
    const int t  = threadIdx.x;
    const int zg = t & 3;                        // 4 slabs each
    const int o4 = blockIdx.x * 64 + (t >> 2);   // float4 index
    const int i  = o4 * 4;

    float4 v = make_float4(0.f, 0.f, 0.f, 0.f);
    #pragma unroll
    for (int j = 0; j < 4; j++) {
        const float4 p = *(const float4*)&g_part[(zg * 4 + j) * BATCH * DM + i];
        v.x += p.x; v.y += p.y; v.z += p.z; v.w += p.w;
    }
    #pragma unroll
    for (int m = 1; m <= 2; m <<= 1) {
        v.x += __shfl_xor_sync(0xFFFFFFFFu, v.x, m);
        v.y += __shfl_xor_sync(0xFFFFFFFFu, v.y, m);
        v.z += __shfl_xor_sync(0xFFFFFFFFu, v.z, m);
        v.w += __shfl_xor_sync(0xFFFFFFFFu, v.w, m);
    }
    if (zg == 0) {
        float4 o;
        o.x = v.x / (1.0f + __expf(-v.x));
        o.y = v.y / (1.0f + __expf(-v.y));
        o.z = v.z / (1.0f + __expf(-v.z));
        o.w = v.w / (1.0f + __expf(-v.w));
        *(float4*)&out[i] = o;
    }
}

extern "C" void kernel_launch(void* const* d_in, const int* in_sizes, int n_in,
                              void* d_out, int out_size)
{
    (void)in_sizes; (void)n_in; (void)out_size;
    const float* xr = (const float*)d_in[0];
    const float* xi = (const float*)d_in[1];
    const float* W  = (const float*)d_in[2];
    const float* Bm = (const float*)d_in[3];
    const float* PC = (const float*)d_in[4];
    const float* PS = (const float*)d_in[5];
    float* out = (float*)d_out;

    dim3 g1(NN / NT, BATCH / BT, ZSPLIT);      // 32 x 8 x 8 = 2048 blocks
    phase1_kernel<<<g1, P1_THREADS>>>(xr, xi, W, Bm);

    combine_kernel<<<BATCH * KTOT / 4 / 128, 256>>>();          // 1024 blocks

    dim3 g2(DM / BN, BATCH / BM, SPLITK);      // 8 x 4 x 16 = 512 blocks
    phase2_kernel<<<g2, 256>>>(PC, PS);

    phase3_kernel<<<BATCH * DM / 4 / 64, 256>>>(out);           // 512 blocks
}

// round 5
// speedup vs baseline: 1.2860x; 1.0930x over previous
#include <cuda_runtime.h>
#include <math.h>

// Problem dims (fixed by setup_inputs)
#define BATCH 256
#define DM    512
#define NN    1024
#define KTOT  (2*NN)

// Phase-1 tiling: 32x32 (batch x neuron) tile, 256 threads, 2x2 per thread,
// d split across blockIdx.z into 8 slabs of 64 (exactly one staged chunk).
#define BT 32
#define NT 32
#define DC 64
#define ZSPLIT 8
#define DPER (DM / ZSPLIT)       // 64 == DC
#define P1_THREADS 256

// Phase-2 tiling (split-K SGEMM)
#define BM 64
#define BN 64
#define BK 16
#define SPLITK 16
#define KCHUNK (KTOT / SPLITK)   // 128

// Scratch (static device globals — no allocation allowed)
__device__ float g_sumsP[ZSPLIT][BATCH * KTOT];   // phase-1 partials per d-slab
__device__ float g_sums[BATCH * KTOT];            // combined sums
__device__ float g_part[SPLITK * BATCH * DM];     // split-K GEMM partials

// ---------------------------------------------------------------------------
// Packed f32x2 helpers (Blackwell)
// ---------------------------------------------------------------------------
__device__ __forceinline__ unsigned long long pack2(float lo, float hi) {
    unsigned long long r;
    asm("mov.b64 %0, {%1, %2};" : "=l"(r) : "f"(lo), "f"(hi));
    return r;
}
__device__ __forceinline__ void unpack2(unsigned long long v, float& lo, float& hi) {
    asm("mov.b64 {%0, %1}, %2;" : "=f"(lo), "=f"(hi) : "l"(v));
}
__device__ __forceinline__ void fma2(unsigned long long& d, unsigned long long a,
                                     unsigned long long b) {
    asm("fma.rn.f32x2 %0, %1, %2, %3;" : "=l"(d) : "l"(a), "l"(b), "l"(d));
}

// ---------------------------------------------------------------------------
// FMA-pipe sincos (no MUFU): magic-number round -> quadrant, Cody-Waite
// reduction to |r| <= pi/4, deg-7 sin / deg-6 cos minimax, branch-free fixup.
// Valid for |theta| < ~1e4 (here |theta| <= ~10).
// ---------------------------------------------------------------------------
__device__ __forceinline__ void sincos_poly(float th, float* so, float* co)
{
    const float MAGIC = 12582912.0f;              // 1.5 * 2^23
    float kf = fmaf(th, 0.63661977236758134f, MAGIC);   // th*2/pi + magic
    const int q = __float_as_int(kf);             // low 2 bits = n mod 4
    kf -= MAGIC;                                  // n as float
    // r = th - n*pi/2  (2-step Cody-Waite)
    float r = fmaf(kf, -1.5707962513e0f, th);     // pi/2 hi
    r = fmaf(kf, -7.5497894159e-8f, r);           // pi/2 lo
    const float u = r * r;
    // sin(r), |r|<=pi/4, deg 7
    float sp = -1.9515295891e-4f;
    sp = fmaf(sp, u,  8.3321608736e-3f);
    sp = fmaf(sp, u, -1.6666654611e-1f);
    sp = fmaf(sp * u, r, r);
    // cos(r), deg 6
    float cp = 2.443315711809948e-5f;
    cp = fmaf(cp, u, -1.388731625493765e-3f);
    cp = fmaf(cp, u,  4.166664568298827e-2f);
    cp = fmaf(cp, u, -0.5f);
    cp = fmaf(cp, u,  1.0f);
    // quadrant fixup
    const bool swap = (q & 1);
    float ss = swap ? cp : sp;
    float cc = swap ? sp : cp;
    const int sgn_s = (q & 2) << 30;
    const int sgn_c = ((q + 1) & 2) << 30;
    *so = __int_as_float(__float_as_int(ss) ^ sgn_s);
    *co = __int_as_float(__float_as_int(cc) ^ sgn_c);
}

// ---------------------------------------------------------------------------
// Phase 1: resonance partial sums over one 64-wide d-slab.
// Grid: (NN/32=32, BATCH/32=8, ZSPLIT=8) = 2048 blocks x 256 threads.
// Per d: 4 sincos -> 3 via MUFU + 1 via FMA-pipe polynomial (pipe balancing).
// ---------------------------------------------------------------------------
__global__ void __launch_bounds__(P1_THREADS) phase1_kernel(
    const float* __restrict__ xr, const float* __restrict__ xi,
    const float* __restrict__ W,  const float* __restrict__ Bm)
{
    __shared__ float xsT[DC][BT + 2];        // [d][b], stride 34
    __shared__ float wbT[DC][2 * NT + 4];    // [d][(w,b) interleaved], stride 132

    const int t  = threadIdx.x;
    const int tn = t & 15;                   // neuron-pair index
    const int tb = t >> 4;                   // batch-pair index
    const int b0 = blockIdx.y * BT;
    const int n0 = blockIdx.x * NT;
    const int z  = blockIdx.z;
    const int d0 = z * DPER;

    // Stage 32 rows x 64 d into transposed smem (8 iters/thread).
    #pragma unroll
    for (int i = t; i < BT * DC; i += P1_THREADS) {
        const int r = i >> 6;
        const int c = i & (DC - 1);
        const int gx = (b0 + r) * DM + d0 + c;
        xsT[c][r] = xr[gx] + xi[gx];
        const int gw = (n0 + r) * DM + d0 + c;
        const float winv = __fdividef(1.0f, 1.0f + fabsf(W[gw]));
        *(float2*)&wbT[c][2 * r] = make_float2(winv, Bm[gw]);
    }
    __syncthreads();

    float aS00 = 0.f, aS01 = 0.f, aS10 = 0.f, aS11 = 0.f;
    float aC00 = 0.f, aC01 = 0.f, aC10 = 0.f, aC11 = 0.f;

    #pragma unroll 8
    for (int d = 0; d < DC; d++) {
        const float2 xv = *(const float2*)&xsT[d][2 * tb];
        const float4 wb = *(const float4*)&wbT[d][4 * tn];
        // wb = (w_n0, b_n0, w_n1, b_n1)
        float s, c;
        __sincosf(fmaf(xv.x, wb.x, wb.y), &s, &c); aS00 += s; aC00 += c;
        __sincosf(fmaf(xv.x, wb.z, wb.w), &s, &c); aS01 += s; aC01 += c;
        __sincosf(fmaf(xv.y, wb.x, wb.y), &s, &c); aS10 += s; aC10 += c;
        sincos_poly(fmaf(xv.y, wb.z, wb.w), &s, &c); aS11 += s; aC11 += c;
    }

    float* outp = g_sumsP[z];
    const int br0 = b0 + 2 * tb, br1 = br0 + 1;
    const int nc0 = n0 + 2 * tn;             // even -> 8B aligned
    *(float2*)&outp[br0 * KTOT + nc0]      = make_float2(aC00, aC01);
    *(float2*)&outp[br1 * KTOT + nc0]      = make_float2(aC10, aC11);
    *(float2*)&outp[br0 * KTOT + NN + nc0] = make_float2(aS00, aS01);
    *(float2*)&outp[br1 * KTOT + NN + nc0] = make_float2(aS10, aS11);
}

// ---------------------------------------------------------------------------
// Combine the 8 d-slab partials. 2 threads per float4 output, shfl merge.
// ---------------------------------------------------------------------------
__global__ void __launch_bounds__(256) combine_kernel()
{
    const int t = threadIdx.x;
    const int zg = t & 1;
    const int o4 = blockIdx.x * 128 + (t >> 1);
    const int i  = o4 * 4;

    float4 v = make_float4(0.f, 0.f, 0.f, 0.f);
    #pragma unroll
    for (int j = 0; j < 4; j++) {
        const float4 p = *(const float4*)&g_sumsP[zg * 4 + j][i];
        v.x += p.x; v.y += p.y; v.z += p.z; v.w += p.w;
    }
    v.x += __shfl_xor_sync(0xFFFFFFFFu, v.x, 1);
    v.y += __shfl_xor_sync(0xFFFFFFFFu, v.y, 1);
    v.z += __shfl_xor_sync(0xFFFFFFFFu, v.z, 1);
    v.w += __shfl_xor_sync(0xFFFFFFFFu, v.w, 1);
    if (zg == 0) *(float4*)&g_sums[i] = v;
}

// ---------------------------------------------------------------------------
// Phase 2: split-K SGEMM with packed f32x2 FMA.
// Grid: (DM/64=8, BATCH/64=4, SPLITK=16) = 512 blocks x 256 threads.
// ---------------------------------------------------------------------------
__global__ void __launch_bounds__(256) phase2_kernel(
    const float* __restrict__ PC, const float* __restrict__ PS)
{
    __shared__ float As[BK][BM + 4];
    __shared__ float Bs[BK][BN + 4];

    const int t  = threadIdx.x;
    const int tx = t & 15;
    const int ty = t >> 4;
    const int m0 = blockIdx.x * BN;
    const int b0 = blockIdx.y * BM;
    const int z  = blockIdx.z;
    const int kbase = z * KCHUNK;

    const float* __restrict__ Wsel = (kbase < NN) ? PC : PS;
    const int koff = (kbase < NN) ? 0 : NN;

    unsigned long long acc2[4][2];
    #pragma unroll
    for (int i = 0; i < 4; i++) { acc2[i][0] = 0ull; acc2[i][1] = 0ull; }

    for (int k0 = kbase; k0 < kbase + KCHUNK; k0 += BK) {
        #pragma unroll
        for (int i = t; i < BM * BK; i += 256) {
            const int r  = i >> 4;
            const int kk = i & 15;
            As[kk][r] = g_sums[(b0 + r) * KTOT + k0 + kk];
        }
        #pragma unroll
        for (int i = t; i < BN * BK; i += 256) {
            const int r  = i >> 4;
            const int kk = i & 15;
            Bs[kk][r] = Wsel[(m0 + r) * NN + (k0 + kk - koff)];
        }
        __syncthreads();

        #pragma unroll
        for (int kk = 0; kk < BK; kk++) {
            const float4 av = *(const float4*)&As[kk][ty * 4];
            const float4 bv = *(const float4*)&Bs[kk][tx * 4];
            const unsigned long long b01 = pack2(bv.x, bv.y);
            const unsigned long long b23 = pack2(bv.z, bv.w);
            const float a[4] = {av.x, av.y, av.z, av.w};
            #pragma unroll
            for (int i = 0; i < 4; i++) {
                const unsigned long long ai = pack2(a[i], a[i]);
                fma2(acc2[i][0], ai, b01);
                fma2(acc2[i][1], ai, b23);
            }
        }
        __syncthreads();
    }

    float* outp = &g_part[z * BATCH * DM];
    #pragma unroll
    for (int i = 0; i < 4; i++) {
        float v0, v1, v2, v3;
        unpack2(acc2[i][0], v0, v1);
        unpack2(acc2[i][1], v2, v3);
        *(float4*)&outp[(b0 + ty * 4 + i) * DM + m0 + tx * 4] =
            make_float4(v0, v1, v2, v3);
    }
}

// ---------------------------------------------------------------------------
// Phase 3: reduce split-K partials + SiLU. 4 threads per float4 output.
// ---------------------------------------------------------------------------
__global__ void __launch_bounds__(256) phase3_kernel(float* __restrict__ out)
{
    const int t  = threadIdx.x;
    const int zg = t & 3;
    const int o4 = blockIdx.x * 64 + (t >> 2);
    const int i  = o4 * 4;

    float4 v = make_float4(0.f, 0.f, 0.f, 0.f);
    #pragma unroll
    for (int j = 0; j < 4; j++) {
        const float4 p = *(const float4*)&g_part[(zg * 4 + j) * BATCH * DM + i];
        v.x += p.x; v.y += p.y; v.z += p.z; v.w += p.w;
    }
    #pragma unroll
    for (int m = 1; m <= 2; m <<= 1) {
        v.x += __shfl_xor_sync(0xFFFFFFFFu, v.x, m);
        v.y += __shfl_xor_sync(0xFFFFFFFFu, v.y, m);
        v.z += __shfl_xor_sync(0xFFFFFFFFu, v.z, m);
        v.w += __shfl_xor_sync(0xFFFFFFFFu, v.w, m);
    }
    if (zg == 0) {
        float4 o;
        o.x = v.x / (1.0f + __expf(-v.x));
        o.y = v.y / (1.0f + __expf(-v.y));
        o.z = v.z / (1.0f + __expf(-v.z));
        o.w = v.w / (1.0f + __expf(-v.w));
        *(float4*)&out[i] = o;
    }
}

extern "C" void kernel_launch(void* const* d_in, const int* in_sizes, int n_in,
                              void* d_out, int out_size)
{
    (void)in_sizes; (void)n_in; (void)out_size;
    const float* xr = (const float*)d_in[0];
    const float* xi = (const float*)d_in[1];
    const float* W  = (const float*)d_in[2];
    const float* Bm = (const float*)d_in[3];
    const float* PC = (const float*)d_in[4];
    const float* PS = (const float*)d_in[5];
    float* out = (float*)d_out;

    dim3 g1(NN / NT, BATCH / BT, ZSPLIT);      // 32 x 8 x 8 = 2048 blocks
    phase1_kernel<<<g1, P1_THREADS>>>(xr, xi, W, Bm);

    combine_kernel<<<BATCH * KTOT / 4 / 128, 256>>>();          // 1024 blocks

    dim3 g2(DM / BN, BATCH / BM, SPLITK);      // 8 x 4 x 16 = 512 blocks
    phase2_kernel<<<g2, 256>>>(PC, PS);

    phase3_kernel<<<BATCH * DM / 4 / 64, 256>>>(out);           // 512 blocks
}